// round 3
// baseline (speedup 1.0000x reference)
#include <cuda_runtime.h>
#include <cuda_bf16.h>
#include <math.h>

#define MAXN   100000
#define MAXNP  (MAXN + 16)
#define FDIM   44
#define F2DIM  88
#define FEATD  1019
#define MAXG   1024
#define MAXE   1000000
#define SCANB  1024
#define MAXNB  ((MAXN + SCANB - 1) / SCANB)

// ---------------- scratch (allocation-free rule: __device__ globals) ----------------
__device__ __align__(256) float g_bufA[MAXNP * F2DIM];
__device__ __align__(256) float g_bufB[MAXNP * F2DIM];
__device__ __align__(256) float g_dinv[MAXN];
__device__ __align__(256) int   g_indeg[MAXN];
__device__ __align__(256) int   g_cursor[MAXN];
__device__ __align__(256) int   g_off[MAXN + 1];
__device__ __align__(256) int2  g_epack[MAXE];          // (src, __float_as_int(norm))
__device__ __align__(256) int   g_partial[MAXNB + 1];
__device__ __align__(256) int   g_bofs[MAXNB + 1];
__device__ __align__(256) int   g_start[MAXG];
__device__ __align__(256) float g_pool[MAXG * FDIM];

// ---------------- f32x2 packed math helpers ----------------
__device__ __forceinline__ unsigned long long ffma2(unsigned long long a,
                                                    unsigned long long b,
                                                    unsigned long long c) {
    unsigned long long d;
    asm("fma.rn.f32x2 %0, %1, %2, %3;" : "=l"(d) : "l"(a), "l"(b), "l"(c));
    return d;
}
__device__ __forceinline__ unsigned long long splat2(float x) {
    unsigned long long d;
    asm("mov.b64 %0, {%1, %2};" : "=l"(d) : "r"(__float_as_uint(x)), "r"(__float_as_uint(x)));
    return d;
}

// ---------------- degree / norm ----------------
__global__ void k_count(const int* __restrict__ dst, int* __restrict__ indeg, int E) {
    int e = blockIdx.x * blockDim.x + threadIdx.x;
    if (e < E) atomicAdd(&indeg[dst[e]], 1);
}
__global__ void k_dinv(const int* __restrict__ indeg, float* __restrict__ dinv, int n) {
    int i = blockIdx.x * blockDim.x + threadIdx.x;
    if (i < n) dinv[i] = rsqrtf(1.0f + (float)indeg[i]);
}

// ---------------- 3-phase parallel exclusive scan ----------------
__global__ void k_scan1(const int* __restrict__ indeg, int* __restrict__ off,
                        int* __restrict__ partial, int n) {
    __shared__ int wsum[32];
    int tid = threadIdx.x, lane = tid & 31, wid = tid >> 5;
    int idx = blockIdx.x * SCANB + tid;
    int v = (idx < n) ? indeg[idx] : 0;
    int incl = v;
    #pragma unroll
    for (int d = 1; d < 32; d <<= 1) {
        int t = __shfl_up_sync(0xffffffffu, incl, d);
        if (lane >= d) incl += t;
    }
    if (lane == 31) wsum[wid] = incl;
    __syncthreads();
    if (wid == 0) {
        int w = wsum[lane];
        #pragma unroll
        for (int d = 1; d < 32; d <<= 1) {
            int t = __shfl_up_sync(0xffffffffu, w, d);
            if (lane >= d) w += t;
        }
        wsum[lane] = w;
    }
    __syncthreads();
    int warpoff = (wid == 0) ? 0 : wsum[wid - 1];
    if (idx < n) off[idx] = warpoff + incl - v;
    if (tid == 0) partial[blockIdx.x] = wsum[31];
}
__global__ void k_scan2(const int* __restrict__ partial, int* __restrict__ bofs, int nb) {
    __shared__ int wsum[32];
    int tid = threadIdx.x, lane = tid & 31, wid = tid >> 5;  // 128 threads (4 warps)
    int v = (tid < nb) ? partial[tid] : 0;
    int incl = v;
    #pragma unroll
    for (int d = 1; d < 32; d <<= 1) {
        int t = __shfl_up_sync(0xffffffffu, incl, d);
        if (lane >= d) incl += t;
    }
    if (lane == 31) wsum[wid] = incl;
    __syncthreads();
    if (wid == 0 && lane < 4) {
        int w = wsum[lane];
        #pragma unroll
        for (int d = 1; d < 4; d <<= 1) {
            int t = __shfl_up_sync(0x0000000fu, w, d);
            if (lane >= d) w += t;
        }
        wsum[lane] = w;
    }
    __syncthreads();
    int warpoff = (wid == 0) ? 0 : wsum[wid - 1];
    if (tid < nb) bofs[tid] = warpoff + incl - v;
}
__global__ void k_scan3(int* __restrict__ off, const int* __restrict__ bofs, int n, int E) {
    int idx = blockIdx.x * blockDim.x + threadIdx.x;
    if (idx < n) off[idx] += bofs[idx >> 10];
    if (idx == 0) off[n] = E;
}

// ---------------- CSR fill: packed (src, norm) ----------------
__global__ void k_fill(const int* __restrict__ src, const int* __restrict__ dst,
                       const float* __restrict__ dinv, const int* __restrict__ off,
                       int* __restrict__ cursor, int2* __restrict__ ep, int E) {
    int e = blockIdx.x * blockDim.x + threadIdx.x;
    if (e >= E) return;
    int s = src[e], d = dst[e];
    int p = off[d] + atomicAdd(&cursor[d], 1);
    ep[p] = make_int2(s, __float_as_int(dinv[s] * dinv[d]));
}

// ---------------- t = act(h) @ W, 8 rows x one float4-out-chunk per thread ----------------
template <int KIN, int KOUT4, int RELU>
__global__ void __launch_bounds__(256) k_mm(const float* __restrict__ h,
                                            const float* __restrict__ W,
                                            float* __restrict__ t, int n) {
    const int R = 8;
    int gid = blockIdx.x * 256 + threadIdx.x;
    int c4 = gid % KOUT4;
    int rb = gid / KOUT4;
    int row0 = rb * R;
    if (row0 >= n) return;

    const ulonglong2* Wv = (const ulonglong2*)W;
    unsigned long long acc0[R], acc1[R];
    #pragma unroll
    for (int r = 0; r < R; r++) { acc0[r] = 0ull; acc1[r] = 0ull; }

    const float4* hp[R];
    #pragma unroll
    for (int r = 0; r < R; r++) {
        int rr = row0 + r; if (rr > n - 1) rr = n - 1;
        hp[r] = (const float4*)(h + (size_t)rr * KIN);
    }

    #pragma unroll 2
    for (int k4 = 0; k4 < KIN / 4; k4++) {
        float4 hv[R];
        #pragma unroll
        for (int r = 0; r < R; r++) {
            float4 v = hp[r][k4];
            if (RELU) {
                v.x = fmaxf(v.x, 0.f); v.y = fmaxf(v.y, 0.f);
                v.z = fmaxf(v.z, 0.f); v.w = fmaxf(v.w, 0.f);
            }
            hv[r] = v;
        }
        #pragma unroll
        for (int kk = 0; kk < 4; kk++) {
            ulonglong2 wv = Wv[(k4 * 4 + kk) * KOUT4 + c4];
            #pragma unroll
            for (int r = 0; r < R; r++) {
                float hs = (kk == 0) ? hv[r].x : (kk == 1) ? hv[r].y
                         : (kk == 2) ? hv[r].z : hv[r].w;
                unsigned long long s = splat2(hs);
                acc0[r] = ffma2(s, wv.x, acc0[r]);
                acc1[r] = ffma2(s, wv.y, acc1[r]);
            }
        }
    }
    #pragma unroll
    for (int r = 0; r < R; r++) {
        int rr = row0 + r;
        if (rr < n) {
            ulonglong2 o; o.x = acc0[r]; o.y = acc1[r];
            ((ulonglong2*)t)[(size_t)rr * KOUT4 + c4] = o;
        }
    }
}

// ---------------- warp-per-node aggregation ----------------
// VW=2 -> F=44 (float2 per lane, lanes 0..21), VW=4 -> F=88 (float4 per lane, lanes 0..21)
template <int VW>
__global__ void __launch_bounds__(256) k_aggr(const float* __restrict__ t,
                                              const int2* __restrict__ ep,
                                              const int* __restrict__ off,
                                              const float* __restrict__ dinv,
                                              const float* __restrict__ bias,
                                              float* __restrict__ out, int n) {
    const int F = VW * 22;
    int gwarp = (blockIdx.x * 256 + threadIdx.x) >> 5;
    if (gwarp >= n) return;
    int lane = threadIdx.x & 31;
    int node = gwarp;
    int c = (lane < 22) ? lane : 21;          // clamp idle lanes onto valid memory

    float dd = dinv[node];
    float sl = dd * dd;

    float acc[VW];
    {
        const float* ts = t + (size_t)node * F + c * VW;
        #pragma unroll
        for (int q = 0; q < VW; q++)
            acc[q] = fmaf(ts[q], sl, bias[c * VW + q]);
    }

    int beg = off[node], end = off[node + 1];
    for (int j0 = beg; j0 < end; j0 += 32) {
        int je = j0 + lane;
        int2 rec = make_int2(0, 0);
        if (je < end) rec = ep[je];
        int cnt = end - j0; if (cnt > 32) cnt = 32;
        for (int k = 0; k < cnt; k++) {
            int   s = __shfl_sync(0xffffffffu, rec.x, k);
            float w = __int_as_float(__shfl_sync(0xffffffffu, rec.y, k));
            const float* vs = t + (size_t)s * F + c * VW;
            if (VW == 2) {
                float2 v = *(const float2*)vs;
                acc[0] = fmaf(v.x, w, acc[0]);
                acc[1] = fmaf(v.y, w, acc[1]);
            } else {
                float4 v = *(const float4*)vs;
                acc[0] = fmaf(v.x, w, acc[0]);
                acc[1] = fmaf(v.y, w, acc[1]);
                acc[2] = fmaf(v.z, w, acc[2]);
                acc[3] = fmaf(v.w, w, acc[3]);
            }
        }
    }

    if (lane < 22) {
        float* op = out + (size_t)node * F + c * VW;
        if (VW == 2) {
            *(float2*)op = make_float2(acc[0], acc[1]);
        } else {
            *(float4*)op = make_float4(acc[0], acc[1], acc[2], acc[3]);
        }
    }
}

// ---------------- pooling over sorted batch ----------------
__global__ void k_seg_starts(const int* __restrict__ batch, int* __restrict__ start, int n) {
    int i = blockIdx.x * blockDim.x + threadIdx.x;
    if (i >= n) return;
    int b = batch[i];
    if (i == 0 || batch[i - 1] != b) start[b] = i;
}
__global__ void k_pool(const float* __restrict__ h, const int* __restrict__ start,
                       float* __restrict__ pool, int n, int G) {
    int gid = blockIdx.x * blockDim.x + threadIdx.x;
    if (gid >= G * FDIM) return;
    int g = gid / FDIM;
    int j = gid - g * FDIM;
    int beg = start[g];
    int end = (g + 1 < G) ? start[g + 1] : n;
    float m = 0.0f;  // relu(h) >= 0
    for (int i = beg; i < end; i++)
        m = fmaxf(m, h[(size_t)i * FDIM + j]);
    pool[g * FDIM + j] = m;
}

// ---------------- final heads: 8 graphs per block ----------------
__global__ void k_final(const float* __restrict__ pool, const float* __restrict__ feat,
                        const float* __restrict__ Wg,  const float* __restrict__ bg,
                        const float* __restrict__ Wf1, const float* __restrict__ bf1,
                        const float* __restrict__ Wf2, const float* __restrict__ bf2,
                        float* __restrict__ out, int G) {
    const int GB = 8;
    int g0 = blockIdx.x * GB;
    int j = threadIdx.x;   // 128
    float acc[GB];
    float bj = bf1[j];
    #pragma unroll
    for (int i = 0; i < GB; i++) acc[i] = bj;
    #pragma unroll 2
    for (int k = 0; k < FEATD; k++) {
        float w = Wf1[k * 128 + j];
        #pragma unroll
        for (int i = 0; i < GB; i++) {
            int g = g0 + i;
            float f = (g < G) ? feat[(size_t)g * FEATD + k] : 0.0f;
            acc[i] = fmaf(f, w, acc[i]);
        }
    }
    float wf2 = Wf2[j];
    __shared__ float red[128];
    __shared__ float sums[GB];
    #pragma unroll
    for (int i = 0; i < GB; i++) {
        red[j] = fmaxf(acc[i], 0.0f) * wf2;
        __syncthreads();
        for (int o = 64; o > 0; o >>= 1) {
            if (j < o) red[j] += red[j + o];
            __syncthreads();
        }
        if (j == 0) sums[i] = red[0];
        __syncthreads();
    }
    if (j < GB) {
        int g = g0 + j;
        if (g < G) {
            float a = bg[0];
            #pragma unroll
            for (int k = 0; k < FDIM; k++)
                a = fmaf(pool[g * FDIM + k], Wg[k], a);
            out[g] = fmaxf(a, 0.0f) + sums[j] + bf2[0];
        }
    }
}

// ----------------------------------------------------------------
extern "C" void kernel_launch(void* const* d_in, const int* in_sizes, int n_in,
                              void* d_out, int out_size) {
    const float* x       = (const float*)d_in[0];
    const int*   ei      = (const int*)  d_in[1];
    const int*   batch   = (const int*)  d_in[2];
    const float* feature = (const float*)d_in[3];
    const float* W1 = (const float*)d_in[4];  const float* b1 = (const float*)d_in[5];
    const float* W2 = (const float*)d_in[6];  const float* b2 = (const float*)d_in[7];
    const float* W3 = (const float*)d_in[8];  const float* b3 = (const float*)d_in[9];
    const float* Wg = (const float*)d_in[10]; const float* bg = (const float*)d_in[11];
    const float* Wf1= (const float*)d_in[12]; const float* bf1= (const float*)d_in[13];
    const float* Wf2= (const float*)d_in[14]; const float* bf2= (const float*)d_in[15];

    const int N = in_sizes[2];
    const int E = in_sizes[1] / 2;
    const int G = in_sizes[3] / FEATD;
    const int NB = (N + SCANB - 1) / SCANB;

    float *A, *B, *dinv, *pool;
    int *indeg, *cursor, *off, *partial, *bofs, *start;
    int2 *ep;
    cudaGetSymbolAddress((void**)&A,      g_bufA);
    cudaGetSymbolAddress((void**)&B,      g_bufB);
    cudaGetSymbolAddress((void**)&dinv,   g_dinv);
    cudaGetSymbolAddress((void**)&indeg,  g_indeg);
    cudaGetSymbolAddress((void**)&cursor, g_cursor);
    cudaGetSymbolAddress((void**)&off,    g_off);
    cudaGetSymbolAddress((void**)&ep,     g_epack);
    cudaGetSymbolAddress((void**)&partial,g_partial);
    cudaGetSymbolAddress((void**)&bofs,   g_bofs);
    cudaGetSymbolAddress((void**)&start,  g_start);
    cudaGetSymbolAddress((void**)&pool,   g_pool);

    const int* src = ei;
    const int* dst = ei + E;
    float* out = (float*)d_out;

    const int T = 256;
    auto blocks = [&](int work) { return (work + T - 1) / T; };

    // ---- CSR build + norms ----
    cudaMemsetAsync(indeg, 0, N * sizeof(int));
    cudaMemsetAsync(cursor, 0, N * sizeof(int));
    k_count<<<blocks(E), T>>>(dst, indeg, E);
    k_dinv <<<blocks(N), T>>>(indeg, dinv, N);
    k_scan1<<<NB, SCANB>>>(indeg, off, partial, N);
    k_scan2<<<1, 128>>>(partial, bofs, NB);
    k_scan3<<<blocks(N), T>>>(off, bofs, N, E);
    k_fill <<<blocks(E), T>>>(src, dst, dinv, off, cursor, ep, E);

    // ---- layer 1: x(44) -> 44 ----
    {
        const int K4 = FDIM / 4;
        int thr = ((N + 7) / 8) * K4;
        k_mm<FDIM, K4, 0><<<blocks(thr), T>>>(x, W1, A, N);
        k_aggr<2><<<(N + 7) / 8, T>>>(A, ep, off, dinv, b1, B, N);
    }
    // ---- layer 2: relu(B)(44) -> 88 ----
    {
        const int K4 = F2DIM / 4;
        int thr = ((N + 7) / 8) * K4;
        k_mm<FDIM, K4, 1><<<blocks(thr), T>>>(B, W2, A, N);
        k_aggr<4><<<(N + 7) / 8, T>>>(A, ep, off, dinv, b2, B, N);
    }
    // ---- layer 3: relu(B)(88) -> 44 ----
    {
        const int K4 = FDIM / 4;
        int thr = ((N + 7) / 8) * K4;
        k_mm<F2DIM, K4, 1><<<blocks(thr), T>>>(B, W3, A, N);
        k_aggr<2><<<(N + 7) / 8, T>>>(A, ep, off, dinv, b3, B, N);
    }

    // ---- pool + heads ----
    k_seg_starts<<<blocks(N), T>>>(batch, start, N);
    k_pool<<<blocks(G * FDIM), T>>>(B, start, pool, N, G);
    k_final<<<(G + 7) / 8, 128>>>(pool, feature, Wg, bg, Wf1, bf1, Wf2, bf2, out, G);
}

// round 4
// speedup vs baseline: 1.4310x; 1.4310x over previous
#include <cuda_runtime.h>
#include <cuda_bf16.h>
#include <math.h>

#define MAXN   100000
#define MAXNP  (MAXN + 16)
#define FDIM   44
#define F2DIM  88
#define K4F    11            // FDIM/4
#define FEATD  1019
#define MAXG   1024
#define MAXE   1000000
#define SCANB  1024
#define MAXNB  ((MAXN + SCANB - 1) / SCANB)

// ---------------- scratch (allocation-free rule: __device__ globals) ----------------
__device__ __align__(256) float g_bufA[MAXNP * F2DIM];
__device__ __align__(256) float g_bufB[MAXNP * F2DIM];
__device__ __align__(256) float g_dinv[MAXN];
__device__ __align__(256) int   g_indeg[MAXN];
__device__ __align__(256) int   g_cursor[MAXN];
__device__ __align__(256) int   g_off[MAXN + 1];
__device__ __align__(256) int2  g_epack[MAXE];          // (src, __float_as_int(norm))
__device__ __align__(256) int   g_partial[MAXNB + 1];
__device__ __align__(256) int   g_bofs[MAXNB + 1];
__device__ __align__(256) int   g_start[MAXG];
__device__ __align__(256) float g_pool[MAXG * FDIM];

// ---------------- f32x2 packed math helpers ----------------
__device__ __forceinline__ unsigned long long ffma2(unsigned long long a,
                                                    unsigned long long b,
                                                    unsigned long long c) {
    unsigned long long d;
    asm("fma.rn.f32x2 %0, %1, %2, %3;" : "=l"(d) : "l"(a), "l"(b), "l"(c));
    return d;
}
__device__ __forceinline__ unsigned long long splat2(float x) {
    unsigned long long d;
    asm("mov.b64 %0, {%1, %2};" : "=l"(d) : "r"(__float_as_uint(x)), "r"(__float_as_uint(x)));
    return d;
}
__device__ __forceinline__ unsigned long long pack2(float lo, float hi) {
    unsigned long long d;
    asm("mov.b64 %0, {%1, %2};" : "=l"(d) : "r"(__float_as_uint(lo)), "r"(__float_as_uint(hi)));
    return d;
}

// ---------------- degree / norm ----------------
__global__ void k_count(const int* __restrict__ dst, int* __restrict__ indeg, int E) {
    int e = blockIdx.x * blockDim.x + threadIdx.x;
    if (e < E) atomicAdd(&indeg[dst[e]], 1);
}
__global__ void k_dinv(const int* __restrict__ indeg, float* __restrict__ dinv,
                       int* __restrict__ cursor, int n) {
    int i = blockIdx.x * blockDim.x + threadIdx.x;
    if (i < n) { dinv[i] = rsqrtf(1.0f + (float)indeg[i]); cursor[i] = 0; }
}

// ---------------- 3-phase parallel exclusive scan ----------------
__global__ void k_scan1(const int* __restrict__ indeg, int* __restrict__ off,
                        int* __restrict__ partial, int n) {
    __shared__ int wsum[32];
    int tid = threadIdx.x, lane = tid & 31, wid = tid >> 5;
    int idx = blockIdx.x * SCANB + tid;
    int v = (idx < n) ? indeg[idx] : 0;
    int incl = v;
    #pragma unroll
    for (int d = 1; d < 32; d <<= 1) {
        int t = __shfl_up_sync(0xffffffffu, incl, d);
        if (lane >= d) incl += t;
    }
    if (lane == 31) wsum[wid] = incl;
    __syncthreads();
    if (wid == 0) {
        int w = wsum[lane];
        #pragma unroll
        for (int d = 1; d < 32; d <<= 1) {
            int t = __shfl_up_sync(0xffffffffu, w, d);
            if (lane >= d) w += t;
        }
        wsum[lane] = w;
    }
    __syncthreads();
    int warpoff = (wid == 0) ? 0 : wsum[wid - 1];
    if (idx < n) off[idx] = warpoff + incl - v;
    if (tid == 0) partial[blockIdx.x] = wsum[31];
}
__global__ void k_scan2(const int* __restrict__ partial, int* __restrict__ bofs, int nb) {
    __shared__ int wsum[32];
    int tid = threadIdx.x, lane = tid & 31, wid = tid >> 5;  // 128 threads
    int v = (tid < nb) ? partial[tid] : 0;
    int incl = v;
    #pragma unroll
    for (int d = 1; d < 32; d <<= 1) {
        int t = __shfl_up_sync(0xffffffffu, incl, d);
        if (lane >= d) incl += t;
    }
    if (lane == 31) wsum[wid] = incl;
    __syncthreads();
    if (wid == 0 && lane < 4) {
        int w = wsum[lane];
        #pragma unroll
        for (int d = 1; d < 4; d <<= 1) {
            int t = __shfl_up_sync(0x0000000fu, w, d);
            if (lane >= d) w += t;
        }
        wsum[lane] = w;
    }
    __syncthreads();
    int warpoff = (wid == 0) ? 0 : wsum[wid - 1];
    if (tid < nb) bofs[tid] = warpoff + incl - v;
}
__global__ void k_scan3(int* __restrict__ off, const int* __restrict__ bofs, int n, int E) {
    int idx = blockIdx.x * blockDim.x + threadIdx.x;
    if (idx < n) off[idx] += bofs[idx >> 10];
    if (idx == 0) off[n] = E;
}

// ---------------- CSR fill: packed (src, norm) ----------------
__global__ void k_fill(const int* __restrict__ src, const int* __restrict__ dst,
                       const float* __restrict__ dinv, const int* __restrict__ off,
                       int* __restrict__ cursor, int2* __restrict__ ep, int E) {
    int e = blockIdx.x * blockDim.x + threadIdx.x;
    if (e >= E) return;
    int s = src[e], d = dst[e];
    int p = off[d] + atomicAdd(&cursor[d], 1);
    ep[p] = make_int2(s, __float_as_int(dinv[s] * dinv[d]));
}

// ---------------- t = act(h) @ W (+bias), 8 rows x one float4-out-chunk per thread ----------------
template <int KIN, int KOUT4, int RELU, int BIAS>
__global__ void __launch_bounds__(256) k_mm(const float* __restrict__ h,
                                            const float* __restrict__ W,
                                            const float* __restrict__ bias,
                                            float* __restrict__ t, int n) {
    const int R = 8;
    int gid = blockIdx.x * 256 + threadIdx.x;
    int c4 = gid % KOUT4;
    int rb = gid / KOUT4;
    int row0 = rb * R;
    if (row0 >= n) return;

    const ulonglong2* Wv = (const ulonglong2*)W;
    unsigned long long binit0 = 0ull, binit1 = 0ull;
    if (BIAS) {
        float4 b4 = ((const float4*)bias)[c4];
        binit0 = pack2(b4.x, b4.y);
        binit1 = pack2(b4.z, b4.w);
    }
    unsigned long long acc0[R], acc1[R];
    #pragma unroll
    for (int r = 0; r < R; r++) { acc0[r] = binit0; acc1[r] = binit1; }

    const float4* hp[R];
    #pragma unroll
    for (int r = 0; r < R; r++) {
        int rr = row0 + r; if (rr > n - 1) rr = n - 1;
        hp[r] = (const float4*)(h + (size_t)rr * KIN);
    }

    #pragma unroll 2
    for (int k4 = 0; k4 < KIN / 4; k4++) {
        float4 hv[R];
        #pragma unroll
        for (int r = 0; r < R; r++) {
            float4 v = hp[r][k4];
            if (RELU) {
                v.x = fmaxf(v.x, 0.f); v.y = fmaxf(v.y, 0.f);
                v.z = fmaxf(v.z, 0.f); v.w = fmaxf(v.w, 0.f);
            }
            hv[r] = v;
        }
        #pragma unroll
        for (int kk = 0; kk < 4; kk++) {
            ulonglong2 wv = Wv[(k4 * 4 + kk) * KOUT4 + c4];
            #pragma unroll
            for (int r = 0; r < R; r++) {
                float hs = (kk == 0) ? hv[r].x : (kk == 1) ? hv[r].y
                         : (kk == 2) ? hv[r].z : hv[r].w;
                unsigned long long s = splat2(hs);
                acc0[r] = ffma2(s, wv.x, acc0[r]);
                acc1[r] = ffma2(s, wv.y, acc1[r]);
            }
        }
    }
    #pragma unroll
    for (int r = 0; r < R; r++) {
        int rr = row0 + r;
        if (rr < n) {
            ulonglong2 o; o.x = acc0[r]; o.y = acc1[r];
            ((ulonglong2*)t)[(size_t)rr * KOUT4 + c4] = o;
        }
    }
}

// ---------------- F=44 aggregation, thread = (node, float4-chunk), MLP-batched gather ----------
// out[node] = [bias +] act(t[node])*dinv^2 + sum_{s in N(node)} act(t[s]) * norm
template <int RELU, int BIAS>
__global__ void __launch_bounds__(256) k_aggr(const float* __restrict__ t,
                                              const int2* __restrict__ ep,
                                              const int* __restrict__ off,
                                              const float* __restrict__ dinv,
                                              const float* __restrict__ bias,
                                              float* __restrict__ out, int n) {
    const int BATCH = 8;
    int gid = blockIdx.x * 256 + threadIdx.x;
    int node = gid / K4F;
    int c4 = gid - node * K4F;
    if (node >= n) return;

    const float4* t4 = (const float4*)t;
    float dd = dinv[node];
    float sl = dd * dd;

    float4 tv = t4[(size_t)node * K4F + c4];
    if (RELU) {
        tv.x = fmaxf(tv.x, 0.f); tv.y = fmaxf(tv.y, 0.f);
        tv.z = fmaxf(tv.z, 0.f); tv.w = fmaxf(tv.w, 0.f);
    }
    float4 acc;
    if (BIAS) {
        float4 b4 = ((const float4*)bias)[c4];
        acc.x = fmaf(tv.x, sl, b4.x); acc.y = fmaf(tv.y, sl, b4.y);
        acc.z = fmaf(tv.z, sl, b4.z); acc.w = fmaf(tv.w, sl, b4.w);
    } else {
        acc.x = tv.x * sl; acc.y = tv.y * sl;
        acc.z = tv.z * sl; acc.w = tv.w * sl;
    }

    int j = off[node], end = off[node + 1];
    // MLP-batched main loop: 8 independent meta loads, then 8 independent gathers
    for (; j + BATCH <= end; j += BATCH) {
        int2 m[BATCH];
        #pragma unroll
        for (int q = 0; q < BATCH; q++) m[q] = ep[j + q];
        float4 v[BATCH];
        #pragma unroll
        for (int q = 0; q < BATCH; q++)
            v[q] = t4[(size_t)m[q].x * K4F + c4];
        #pragma unroll
        for (int q = 0; q < BATCH; q++) {
            float w = __int_as_float(m[q].y);
            float4 x = v[q];
            if (RELU) {
                x.x = fmaxf(x.x, 0.f); x.y = fmaxf(x.y, 0.f);
                x.z = fmaxf(x.z, 0.f); x.w = fmaxf(x.w, 0.f);
            }
            acc.x = fmaf(x.x, w, acc.x); acc.y = fmaf(x.y, w, acc.y);
            acc.z = fmaf(x.z, w, acc.z); acc.w = fmaf(x.w, w, acc.w);
        }
    }
    // tail (<=7 edges): still batch the loads
    {
        int rem = end - j;
        int2 m[BATCH - 1];
        float4 v[BATCH - 1];
        #pragma unroll
        for (int q = 0; q < BATCH - 1; q++)
            if (q < rem) m[q] = ep[j + q];
        #pragma unroll
        for (int q = 0; q < BATCH - 1; q++)
            if (q < rem) v[q] = t4[(size_t)m[q].x * K4F + c4];
        #pragma unroll
        for (int q = 0; q < BATCH - 1; q++)
            if (q < rem) {
                float w = __int_as_float(m[q].y);
                float4 x = v[q];
                if (RELU) {
                    x.x = fmaxf(x.x, 0.f); x.y = fmaxf(x.y, 0.f);
                    x.z = fmaxf(x.z, 0.f); x.w = fmaxf(x.w, 0.f);
                }
                acc.x = fmaf(x.x, w, acc.x); acc.y = fmaf(x.y, w, acc.y);
                acc.z = fmaf(x.z, w, acc.z); acc.w = fmaf(x.w, w, acc.w);
            }
    }
    ((float4*)out)[(size_t)node * K4F + c4] = acc;
}

// ---------------- pooling over sorted batch (relu fused, 4-way MLP) ----------------
__global__ void k_seg_starts(const int* __restrict__ batch, int* __restrict__ start, int n) {
    int i = blockIdx.x * blockDim.x + threadIdx.x;
    if (i >= n) return;
    int b = batch[i];
    if (i == 0 || batch[i - 1] != b) start[b] = i;
}
__global__ void k_pool(const float* __restrict__ h, const int* __restrict__ start,
                       float* __restrict__ pool, int n, int G) {
    int gid = blockIdx.x * blockDim.x + threadIdx.x;
    if (gid >= G * FDIM) return;
    int g = gid / FDIM;
    int j = gid - g * FDIM;
    int beg = start[g];
    int end = (g + 1 < G) ? start[g + 1] : n;
    float m0 = 0.f, m1 = 0.f, m2 = 0.f, m3 = 0.f;   // relu identity
    int i = beg;
    for (; i + 4 <= end; i += 4) {
        float a = h[(size_t)(i + 0) * FDIM + j];
        float b = h[(size_t)(i + 1) * FDIM + j];
        float c = h[(size_t)(i + 2) * FDIM + j];
        float d = h[(size_t)(i + 3) * FDIM + j];
        m0 = fmaxf(m0, a); m1 = fmaxf(m1, b);
        m2 = fmaxf(m2, c); m3 = fmaxf(m3, d);
    }
    for (; i < end; i++) m0 = fmaxf(m0, h[(size_t)i * FDIM + j]);
    pool[g * FDIM + j] = fmaxf(fmaxf(m0, m1), fmaxf(m2, m3));
}

// ---------------- final heads: 8 graphs per block ----------------
__global__ void k_final(const float* __restrict__ pool, const float* __restrict__ feat,
                        const float* __restrict__ Wg,  const float* __restrict__ bg,
                        const float* __restrict__ Wf1, const float* __restrict__ bf1,
                        const float* __restrict__ Wf2, const float* __restrict__ bf2,
                        float* __restrict__ out, int G) {
    const int GB = 8;
    int g0 = blockIdx.x * GB;
    int j = threadIdx.x;   // 128
    float acc[GB];
    float bj = bf1[j];
    #pragma unroll
    for (int i = 0; i < GB; i++) acc[i] = bj;
    #pragma unroll 2
    for (int k = 0; k < FEATD; k++) {
        float w = Wf1[k * 128 + j];
        #pragma unroll
        for (int i = 0; i < GB; i++) {
            int g = g0 + i;
            float f = (g < G) ? feat[(size_t)g * FEATD + k] : 0.0f;
            acc[i] = fmaf(f, w, acc[i]);
        }
    }
    float wf2 = Wf2[j];
    __shared__ float red[128];
    __shared__ float sums[GB];
    #pragma unroll
    for (int i = 0; i < GB; i++) {
        red[j] = fmaxf(acc[i], 0.0f) * wf2;
        __syncthreads();
        for (int o = 64; o > 0; o >>= 1) {
            if (j < o) red[j] += red[j + o];
            __syncthreads();
        }
        if (j == 0) sums[i] = red[0];
        __syncthreads();
    }
    if (j < GB) {
        int g = g0 + j;
        if (g < G) {
            float a = bg[0];
            #pragma unroll
            for (int k = 0; k < FDIM; k++)
                a = fmaf(pool[g * FDIM + k], Wg[k], a);
            out[g] = fmaxf(a, 0.0f) + sums[j] + bf2[0];
        }
    }
}

// ----------------------------------------------------------------
extern "C" void kernel_launch(void* const* d_in, const int* in_sizes, int n_in,
                              void* d_out, int out_size) {
    const float* x       = (const float*)d_in[0];
    const int*   ei      = (const int*)  d_in[1];
    const int*   batch   = (const int*)  d_in[2];
    const float* feature = (const float*)d_in[3];
    const float* W1 = (const float*)d_in[4];  const float* b1 = (const float*)d_in[5];
    const float* W2 = (const float*)d_in[6];  const float* b2 = (const float*)d_in[7];
    const float* W3 = (const float*)d_in[8];  const float* b3 = (const float*)d_in[9];
    const float* Wg = (const float*)d_in[10]; const float* bg = (const float*)d_in[11];
    const float* Wf1= (const float*)d_in[12]; const float* bf1= (const float*)d_in[13];
    const float* Wf2= (const float*)d_in[14]; const float* bf2= (const float*)d_in[15];

    const int N = in_sizes[2];
    const int E = in_sizes[1] / 2;
    const int G = in_sizes[3] / FEATD;
    const int NB = (N + SCANB - 1) / SCANB;

    float *A, *B, *dinv, *pool;
    int *indeg, *cursor, *off, *partial, *bofs, *start;
    int2 *ep;
    cudaGetSymbolAddress((void**)&A,      g_bufA);
    cudaGetSymbolAddress((void**)&B,      g_bufB);
    cudaGetSymbolAddress((void**)&dinv,   g_dinv);
    cudaGetSymbolAddress((void**)&indeg,  g_indeg);
    cudaGetSymbolAddress((void**)&cursor, g_cursor);
    cudaGetSymbolAddress((void**)&off,    g_off);
    cudaGetSymbolAddress((void**)&ep,     g_epack);
    cudaGetSymbolAddress((void**)&partial,g_partial);
    cudaGetSymbolAddress((void**)&bofs,   g_bofs);
    cudaGetSymbolAddress((void**)&start,  g_start);
    cudaGetSymbolAddress((void**)&pool,   g_pool);

    const int* src = ei;
    const int* dst = ei + E;
    float* out = (float*)d_out;

    const int T = 256;
    auto blocks = [&](int work) { return (work + T - 1) / T; };

    // ---- CSR build + norms ----
    cudaMemsetAsync(indeg, 0, N * sizeof(int));
    k_count<<<blocks(E), T>>>(dst, indeg, E);
    k_dinv <<<blocks(N), T>>>(indeg, dinv, cursor, N);
    k_scan1<<<NB, SCANB>>>(indeg, off, partial, N);
    k_scan2<<<1, 128>>>(partial, bofs, NB);
    k_scan3<<<blocks(N), T>>>(off, bofs, N, E);
    k_fill <<<blocks(E), T>>>(src, dst, dinv, off, cursor, ep, E);

    // Pipeline (all aggregations at F=44 via Agg(HW)=Agg(H)W):
    // 1. A = x @ W1                       (44 -> 44)
    // 2. B = Agg(A) + b1                  (44)
    // 3. A = Agg(relu(B))                 (44)   [layer2 agg moved before its mm]
    // 4. B = A @ W2 + b2                  (44 -> 88)
    // 5. A = relu(B) @ W3                 (88 -> 44)
    // 6. B = Agg(A) + b3                  (44)
    // 7. pool = segmax(relu(B)); heads
    {
        int thr = ((N + 7) / 8) * K4F;
        k_mm<FDIM, K4F, 0, 0><<<blocks(thr), T>>>(x, W1, nullptr, A, N);
    }
    k_aggr<0, 1><<<blocks(N * K4F), T>>>(A, ep, off, dinv, b1, B, N);
    k_aggr<1, 0><<<blocks(N * K4F), T>>>(B, ep, off, dinv, nullptr, A, N);
    {
        int thr = ((N + 7) / 8) * (F2DIM / 4);
        k_mm<FDIM, F2DIM / 4, 0, 1><<<blocks(thr), T>>>(A, W2, b2, B, N);
    }
    {
        int thr = ((N + 7) / 8) * K4F;
        k_mm<F2DIM, K4F, 1, 0><<<blocks(thr), T>>>(B, W3, nullptr, A, N);
    }
    k_aggr<0, 1><<<blocks(N * K4F), T>>>(A, ep, off, dinv, b3, B, N);

    // ---- pool + heads ----
    k_seg_starts<<<blocks(N), T>>>(batch, start, N);
    k_pool<<<blocks(G * FDIM), T>>>(B, start, pool, N, G);
    k_final<<<(G + 7) / 8, 128>>>(pool, feature, Wg, bg, Wf1, bf1, Wf2, bf2, out, G);
}